// round 3
// baseline (speedup 1.0000x reference)
#include <cuda_runtime.h>
#include <cstddef>

#define NN    100000
#define FIN   128
#define FHID  128
#define FOUT  64
#define EMAX  1600000

typedef unsigned long long u64;

// ---------------- f32x2 packed-FMA helpers ---------------------------------
__device__ __forceinline__ u64 pk(float lo, float hi) {
    u64 r; asm("mov.b64 %0,{%1,%2};" : "=l"(r) : "f"(lo), "f"(hi)); return r;
}
__device__ __forceinline__ void f2(u64& d, u64 a, u64 b) {
    asm("fma.rn.f32x2 %0,%1,%2,%0;" : "+l"(d) : "l"(a), "l"(b));
}
__device__ __forceinline__ void upk(float& lo, float& hi, u64 v) {
    asm("mov.b64 {%0,%1},%2;" : "=f"(lo), "=f"(hi) : "l"(v));
}

// ---------------- static scratch ------------------------------------------
__device__ int   g_deg[NN];
__device__ int   g_offs[NN];
__device__ int   g_cursor[NN];
__device__ int   g_csr[EMAX];
__device__ float g_dis[NN];
__device__ __align__(128) float g_h1s[(size_t)NN * FHID];
__device__ __align__(128) float g_h1f[(size_t)NN * FHID];
__device__ __align__(128) float g_h2s[(size_t)NN * FOUT];
__device__ int   g_bsum[1024];

// ---------------- degree --------------------------------------------------
__global__ void zero_deg_kernel(int M) {
    int t = blockIdx.x * blockDim.x + threadIdx.x;
    if (t < M) g_deg[t] = 0;
}
__global__ void degree_kernel(const int* __restrict__ col, int E) {
    int t = blockIdx.x * blockDim.x + threadIdx.x;
    if (t < E) atomicAdd(&g_deg[col[t]], 1);
}

// ---------------- 3-pass exclusive scan over g_deg --------------------------
__global__ void scan_pass1(int* __restrict__ bsum, int M) {
    __shared__ int sh[8];
    int b = blockIdx.x, t = threadIdx.x;
    int base = b * 1024;
    int v = 0;
#pragma unroll
    for (int k = 0; k < 4; k++) {
        int i = base + t + k * 256;
        if (i < M) v += g_deg[i];
    }
#pragma unroll
    for (int d = 16; d; d >>= 1) v += __shfl_down_sync(0xffffffffu, v, d);
    if ((t & 31) == 0) sh[t >> 5] = v;
    __syncthreads();
    if (t < 8) {
        int x = sh[t];
#pragma unroll
        for (int d = 4; d; d >>= 1) x += __shfl_down_sync(0xffu, x, d);
        if (t == 0) bsum[b] = x;
    }
}
// pass2: shuffle-based exclusive scan of block sums (nb <= 1024)
__global__ void scan_pass2(int* __restrict__ bsum, int nb) {
    __shared__ int ws[32];
    int t = threadIdx.x, lane = t & 31, wid = t >> 5;
    int v = (t < nb) ? bsum[t] : 0;
    int inc = v;
#pragma unroll
    for (int d = 1; d < 32; d <<= 1) {
        int n = __shfl_up_sync(0xffffffffu, inc, d);
        if (lane >= d) inc += n;
    }
    if (lane == 31) ws[wid] = inc;
    __syncthreads();
    if (wid == 0) {
        int x = ws[lane];
        int ix = x;
#pragma unroll
        for (int d = 1; d < 32; d <<= 1) {
            int n = __shfl_up_sync(0xffffffffu, ix, d);
            if (lane >= d) ix += n;
        }
        ws[lane] = ix - x;
    }
    __syncthreads();
    if (t < nb) bsum[t] = inc - v + ws[wid];
}
// pass3: per-chunk exclusive scan + chunk base; also dis, cursor init
__global__ void scan_pass3(const int* __restrict__ bsumExc, int M) {
    __shared__ int wsum[32];
    int t = threadIdx.x, b = blockIdx.x;
    int i = b * 1024 + t;
    int v = (i < M) ? g_deg[i] : 0;
    int lane = t & 31, wid = t >> 5;
    int inc = v;
#pragma unroll
    for (int d = 1; d < 32; d <<= 1) {
        int n = __shfl_up_sync(0xffffffffu, inc, d);
        if (lane >= d) inc += n;
    }
    if (lane == 31) wsum[wid] = inc;
    __syncthreads();
    if (wid == 0) {
        int x = wsum[lane];
        int ix = x;
#pragma unroll
        for (int d = 1; d < 32; d <<= 1) {
            int n = __shfl_up_sync(0xffffffffu, ix, d);
            if (lane >= d) ix += n;
        }
        wsum[lane] = ix - x;
    }
    __syncthreads();
    if (i < M) {
        int excl = inc - v + wsum[wid] + bsumExc[b];
        g_offs[i]   = excl;
        g_cursor[i] = excl;
        g_dis[i]    = rsqrtf((float)(v + 1));
    }
}

// ---------------- CSR placement -------------------------------------------
__global__ void place_kernel(const int* __restrict__ rows,
                             const int* __restrict__ cols, int E) {
    int e = blockIdx.x * blockDim.x + threadIdx.x;
    if (e < E) {
        int c = cols[e];
        int p = atomicAdd(&g_cursor[c], 1);
        g_csr[p] = rows[e];
    }
}

// -------- packed-f32x2 SGEMM, C = dis[i] * (A @ W), A [M,128], W [128,BN] ---
template <int BN, int TN>
__global__ void __launch_bounds__(256, 2)
gemm_kernel(const float* __restrict__ A,
            const float* __restrict__ W,
            float* __restrict__ C, int M)
{
    constexpr int BM = 128, BK = 16, TM = 8;
    constexpr int BMP = BM + 4;
    __shared__ float As[BK][BMP];
    __shared__ float Bs[BK][BN];

    const int tid = threadIdx.x;
    const int tx  = tid & 15;
    const int ty  = tid >> 4;
    const int bm0 = blockIdx.x * BM;

    const int arow = tid >> 2;
    const int acol = (tid & 3) << 2;

    constexpr int BCOLS4 = BN / 4;
    constexpr int BRPP   = 256 / BCOLS4;
    constexpr int BPASS  = BK / BRPP;
    const int brow = tid / BCOLS4;
    const int bcol = (tid % BCOLS4) << 2;

    // packed accumulators: row-pairs x TN columns
    u64 acc2[TM / 2][TN];
#pragma unroll
    for (int i = 0; i < TM / 2; i++)
#pragma unroll
        for (int j = 0; j < TN; j++) acc2[i][j] = 0ull;

    for (int kk = 0; kk < 128; kk += BK) {
#pragma unroll
        for (int p = 0; p < 2; p++) {
            int r = bm0 + arow + p * 64;
            float4 v = make_float4(0.f, 0.f, 0.f, 0.f);
            if (r < M) v = *(const float4*)(A + (size_t)r * 128 + kk + acol);
            As[acol + 0][arow + p * 64] = v.x;
            As[acol + 1][arow + p * 64] = v.y;
            As[acol + 2][arow + p * 64] = v.z;
            As[acol + 3][arow + p * 64] = v.w;
        }
#pragma unroll
        for (int p = 0; p < BPASS; p++) {
            int kr = brow + p * BRPP;
            *(float4*)&Bs[kr][bcol] =
                *(const float4*)(W + (size_t)(kk + kr) * BN + bcol);
        }
        __syncthreads();

#pragma unroll
        for (int k = 0; k < BK; k++) {
            float4 a0 = *(const float4*)&As[k][ty * TM];
            float4 a1 = *(const float4*)&As[k][ty * TM + 4];
            u64 ap[4];
            ap[0] = pk(a0.x, a0.y);
            ap[1] = pk(a0.z, a0.w);
            ap[2] = pk(a1.x, a1.y);
            ap[3] = pk(a1.z, a1.w);

            u64 bb[TN];
            {
                float4 b0 = *(const float4*)&Bs[k][tx * TN];
                bb[0] = pk(b0.x, b0.x);
                bb[1] = pk(b0.y, b0.y);
                bb[2] = pk(b0.z, b0.z);
                bb[3] = pk(b0.w, b0.w);
                if (TN == 8) {
                    float4 b1v = *(const float4*)&Bs[k][tx * TN + 4];
                    bb[4] = pk(b1v.x, b1v.x);
                    bb[5] = pk(b1v.y, b1v.y);
                    bb[6] = pk(b1v.z, b1v.z);
                    bb[7] = pk(b1v.w, b1v.w);
                }
            }
#pragma unroll
            for (int i = 0; i < TM / 2; i++)
#pragma unroll
                for (int j = 0; j < TN; j++)
                    f2(acc2[i][j], ap[i], bb[j]);
        }
        __syncthreads();
    }

    // epilogue: unpack row pairs, scale by dis, store
#pragma unroll
    for (int ip = 0; ip < TM / 2; ip++) {
        float lo[TN], hi[TN];
#pragma unroll
        for (int j = 0; j < TN; j++) upk(lo[j], hi[j], acc2[ip][j]);
        int r0 = bm0 + ty * TM + 2 * ip;
        int r1 = r0 + 1;
        if (r0 < M) {
            float d = g_dis[r0];
            float* cp = C + (size_t)r0 * BN + tx * TN;
            float4 o; o.x = lo[0] * d; o.y = lo[1] * d; o.z = lo[2] * d; o.w = lo[3] * d;
            *(float4*)cp = o;
            if (TN == 8) {
                float4 o1; o1.x = lo[4] * d; o1.y = lo[5] * d; o1.z = lo[6] * d; o1.w = lo[7] * d;
                *(float4*)(cp + 4) = o1;
            }
        }
        if (r1 < M) {
            float d = g_dis[r1];
            float* cp = C + (size_t)r1 * BN + tx * TN;
            float4 o; o.x = hi[0] * d; o.y = hi[1] * d; o.z = hi[2] * d; o.w = hi[3] * d;
            *(float4*)cp = o;
            if (TN == 8) {
                float4 o1; o1.x = hi[4] * d; o1.y = hi[5] * d; o1.z = hi[6] * d; o1.w = hi[7] * d;
                *(float4*)(cp + 4) = o1;
            }
        }
    }
}

// ------- agg1: warp/node, h1f = relu(dis*(sum_nbr h1s + h1s[self]) + b1) ---
__global__ void __launch_bounds__(256)
agg1_kernel(const float* __restrict__ b1, int M) {
    int w    = (blockIdx.x * 256 + threadIdx.x) >> 5;
    int lane = threadIdx.x & 31;
    if (w >= M) return;
    int beg = g_offs[w];
    int end = beg + g_deg[w];
    const float4* h = (const float4*)g_h1s;
    float4 s = __ldg(h + (size_t)w * 32 + lane);
    for (int j0 = beg; j0 < end; j0 += 32) {
        int rem = end - j0;
        int cnt = rem < 32 ? rem : 32;
        int myi = (lane < rem) ? __ldg(g_csr + j0 + lane) : 0;
        int j = 0;
        for (; j + 4 <= cnt; j += 4) {
            int s0 = __shfl_sync(0xffffffffu, myi, j);
            int s1 = __shfl_sync(0xffffffffu, myi, j + 1);
            int s2 = __shfl_sync(0xffffffffu, myi, j + 2);
            int s3 = __shfl_sync(0xffffffffu, myi, j + 3);
            float4 v0 = __ldg(h + (size_t)s0 * 32 + lane);
            float4 v1 = __ldg(h + (size_t)s1 * 32 + lane);
            float4 v2 = __ldg(h + (size_t)s2 * 32 + lane);
            float4 v3 = __ldg(h + (size_t)s3 * 32 + lane);
            s.x += (v0.x + v1.x) + (v2.x + v3.x);
            s.y += (v0.y + v1.y) + (v2.y + v3.y);
            s.z += (v0.z + v1.z) + (v2.z + v3.z);
            s.w += (v0.w + v1.w) + (v2.w + v3.w);
        }
        for (; j < cnt; j++) {
            int si = __shfl_sync(0xffffffffu, myi, j);
            float4 v = __ldg(h + (size_t)si * 32 + lane);
            s.x += v.x; s.y += v.y; s.z += v.z; s.w += v.w;
        }
    }
    float  d = g_dis[w];
    float4 b = __ldg((const float4*)b1 + lane);
    float4 o;
    o.x = fmaxf(fmaf(d, s.x, b.x), 0.f);
    o.y = fmaxf(fmaf(d, s.y, b.y), 0.f);
    o.z = fmaxf(fmaf(d, s.z, b.z), 0.f);
    o.w = fmaxf(fmaf(d, s.w, b.w), 0.f);
    ((float4*)g_h1f)[(size_t)w * 32 + lane] = o;
}

// ------- agg2: half-warp/node, out = dis*(sum_nbr h2s + h2s[self]) + b2 ----
__global__ void __launch_bounds__(256)
agg2_kernel(float* __restrict__ out, const float* __restrict__ b2, int M) {
    int tid  = blockIdx.x * 256 + threadIdx.x;
    int node = tid >> 4;
    int lane = threadIdx.x & 31;
    int l16  = lane & 15;
    unsigned mask = 0xFFFFu << (lane & 16);
    bool valid = node < M;
    int beg = 0, end = 0;
    if (valid) { beg = g_offs[node]; end = beg + g_deg[node]; }
    const float4* h = (const float4*)g_h2s;
    float4 s = valid ? __ldg(h + (size_t)node * 16 + l16)
                     : make_float4(0.f, 0.f, 0.f, 0.f);
    for (int j0 = beg; j0 < end; j0 += 16) {
        int rem = end - j0;
        int cnt = rem < 16 ? rem : 16;
        int myi = (l16 < rem) ? __ldg(g_csr + j0 + l16) : 0;
        int j = 0;
        for (; j + 4 <= cnt; j += 4) {
            int s0 = __shfl_sync(mask, myi, j,     16);
            int s1 = __shfl_sync(mask, myi, j + 1, 16);
            int s2 = __shfl_sync(mask, myi, j + 2, 16);
            int s3 = __shfl_sync(mask, myi, j + 3, 16);
            float4 v0 = __ldg(h + (size_t)s0 * 16 + l16);
            float4 v1 = __ldg(h + (size_t)s1 * 16 + l16);
            float4 v2 = __ldg(h + (size_t)s2 * 16 + l16);
            float4 v3 = __ldg(h + (size_t)s3 * 16 + l16);
            s.x += (v0.x + v1.x) + (v2.x + v3.x);
            s.y += (v0.y + v1.y) + (v2.y + v3.y);
            s.z += (v0.z + v1.z) + (v2.z + v3.z);
            s.w += (v0.w + v1.w) + (v2.w + v3.w);
        }
        for (; j < cnt; j++) {
            int si = __shfl_sync(mask, myi, j, 16);
            float4 v = __ldg(h + (size_t)si * 16 + l16);
            s.x += v.x; s.y += v.y; s.z += v.z; s.w += v.w;
        }
    }
    if (valid) {
        float  d = g_dis[node];
        float4 b = __ldg((const float4*)b2 + l16);
        float4 o;
        o.x = fmaf(d, s.x, b.x);
        o.y = fmaf(d, s.y, b.y);
        o.z = fmaf(d, s.z, b.z);
        o.w = fmaf(d, s.w, b.w);
        ((float4*)out)[(size_t)node * 16 + l16] = o;
    }
}

// ---------------- launch ----------------------------------------------------
extern "C" void kernel_launch(void* const* d_in, const int* in_sizes, int n_in,
                              void* d_out, int out_size) {
    const float* x  = (const float*)d_in[0];
    const int*   ei = (const int*)  d_in[1];
    const float* W1 = (const float*)d_in[2];
    const float* b1 = (const float*)d_in[3];
    const float* W2 = (const float*)d_in[4];
    const float* b2 = (const float*)d_in[5];
    float* out = (float*)d_out;

    const int M = in_sizes[0] / FIN;
    const int E = in_sizes[1] / 2;
    const int* rows = ei;
    const int* cols = ei + E;

    float *h1s, *h1f, *h2s;
    int* bsum;
    cudaGetSymbolAddress((void**)&h1s,  g_h1s);
    cudaGetSymbolAddress((void**)&h1f,  g_h1f);
    cudaGetSymbolAddress((void**)&h2s,  g_h2s);
    cudaGetSymbolAddress((void**)&bsum, g_bsum);

    const int nb = (M + 1023) / 1024;

    // CSR build
    zero_deg_kernel<<<(M + 255) / 256, 256>>>(M);
    degree_kernel<<<(E + 255) / 256, 256>>>(cols, E);
    scan_pass1<<<nb, 256>>>(bsum, M);
    scan_pass2<<<1, 1024>>>(bsum, nb);
    scan_pass3<<<nb, 1024>>>(bsum, M);
    place_kernel<<<(E + 255) / 256, 256>>>(rows, cols, E);

    // layer 1
    gemm_kernel<128, 8><<<(M + 127) / 128, 256>>>(x, W1, h1s, M);
    agg1_kernel<<<(M * 32 + 255) / 256, 256>>>(b1, M);

    // layer 2
    gemm_kernel<64, 4><<<(M + 127) / 128, 256>>>(h1f, W2, h2s, M);
    agg2_kernel<<<(M * 16 + 255) / 256, 256>>>(out, b2, M);
}

// round 4
// speedup vs baseline: 1.1184x; 1.1184x over previous
#include <cuda_runtime.h>
#include <cuda_fp16.h>
#include <cstddef>

#define NN    100000
#define FIN   128
#define FHID  128
#define FOUT  64
#define EMAX  1600000

// ---------------- static scratch ------------------------------------------
__device__ int   g_deg[NN];
__device__ int   g_offs[NN];
__device__ int   g_cursor[NN];
__device__ int   g_csr[EMAX];
__device__ float g_dis[NN];
__device__ __align__(128) __half g_h1s[(size_t)NN * FHID];  // fp16 messages L1
__device__ __align__(128) float  g_h1f[(size_t)NN * FHID];  // fp32 layer-1 output
__device__ __align__(128) __half g_h2s[(size_t)NN * FOUT];  // fp16 messages L2
__device__ int   g_bsum[1024];

// ---------------- helpers ---------------------------------------------------
__device__ __forceinline__ void acc_h4(float4& s, uint2 v) {
    float2 fa = __half22float2(*(__half2*)&v.x);
    float2 fb = __half22float2(*(__half2*)&v.y);
    s.x += fa.x; s.y += fa.y; s.z += fb.x; s.w += fb.y;
}
__device__ __forceinline__ uint2 pack_h4(float a, float b, float c, float d) {
    uint2 r;
    __half2 h0 = __floats2half2_rn(a, b);
    __half2 h1 = __floats2half2_rn(c, d);
    r.x = *(unsigned*)&h0;
    r.y = *(unsigned*)&h1;
    return r;
}

// ---------------- degree --------------------------------------------------
__global__ void zero_deg_kernel(int M) {
    int t = blockIdx.x * blockDim.x + threadIdx.x;
    if (t < M) g_deg[t] = 0;
}
__global__ void degree_kernel(const int* __restrict__ col, int E) {
    int t = blockIdx.x * blockDim.x + threadIdx.x;
    if (t < E) atomicAdd(&g_deg[col[t]], 1);
}

// ---------------- 3-pass exclusive scan over g_deg --------------------------
__global__ void scan_pass1(int* __restrict__ bsum, int M) {
    __shared__ int sh[8];
    int b = blockIdx.x, t = threadIdx.x;
    int base = b * 1024;
    int v = 0;
#pragma unroll
    for (int k = 0; k < 4; k++) {
        int i = base + t + k * 256;
        if (i < M) v += g_deg[i];
    }
#pragma unroll
    for (int d = 16; d; d >>= 1) v += __shfl_down_sync(0xffffffffu, v, d);
    if ((t & 31) == 0) sh[t >> 5] = v;
    __syncthreads();
    if (t < 8) {
        int x = sh[t];
#pragma unroll
        for (int d = 4; d; d >>= 1) x += __shfl_down_sync(0xffu, x, d);
        if (t == 0) bsum[b] = x;
    }
}
__global__ void scan_pass2(int* __restrict__ bsum, int nb) {
    __shared__ int ws[32];
    int t = threadIdx.x, lane = t & 31, wid = t >> 5;
    int v = (t < nb) ? bsum[t] : 0;
    int inc = v;
#pragma unroll
    for (int d = 1; d < 32; d <<= 1) {
        int n = __shfl_up_sync(0xffffffffu, inc, d);
        if (lane >= d) inc += n;
    }
    if (lane == 31) ws[wid] = inc;
    __syncthreads();
    if (wid == 0) {
        int x = ws[lane];
        int ix = x;
#pragma unroll
        for (int d = 1; d < 32; d <<= 1) {
            int n = __shfl_up_sync(0xffffffffu, ix, d);
            if (lane >= d) ix += n;
        }
        ws[lane] = ix - x;
    }
    __syncthreads();
    if (t < nb) bsum[t] = inc - v + ws[wid];
}
__global__ void scan_pass3(const int* __restrict__ bsumExc, int M) {
    __shared__ int wsum[32];
    int t = threadIdx.x, b = blockIdx.x;
    int i = b * 1024 + t;
    int v = (i < M) ? g_deg[i] : 0;
    int lane = t & 31, wid = t >> 5;
    int inc = v;
#pragma unroll
    for (int d = 1; d < 32; d <<= 1) {
        int n = __shfl_up_sync(0xffffffffu, inc, d);
        if (lane >= d) inc += n;
    }
    if (lane == 31) wsum[wid] = inc;
    __syncthreads();
    if (wid == 0) {
        int x = wsum[lane];
        int ix = x;
#pragma unroll
        for (int d = 1; d < 32; d <<= 1) {
            int n = __shfl_up_sync(0xffffffffu, ix, d);
            if (lane >= d) ix += n;
        }
        wsum[lane] = ix - x;
    }
    __syncthreads();
    if (i < M) {
        int excl = inc - v + wsum[wid] + bsumExc[b];
        g_offs[i]   = excl;
        g_cursor[i] = excl;
        g_dis[i]    = rsqrtf((float)(v + 1));
    }
}

// ---------------- CSR placement -------------------------------------------
__global__ void place_kernel(const int* __restrict__ rows,
                             const int* __restrict__ cols, int E) {
    int e = blockIdx.x * blockDim.x + threadIdx.x;
    if (e < E) {
        int c = cols[e];
        int p = atomicAdd(&g_cursor[c], 1);
        g_csr[p] = rows[e];
    }
}

// -------- SGEMM, Ch[i] = half(dis[i] * (A @ W)), A [M,128], W [128,BN] ------
template <int BN, int TN>
__global__ void __launch_bounds__(256, 2)
gemm_kernel(const float* __restrict__ A,
            const float* __restrict__ W,
            __half* __restrict__ Ch, int M)
{
    constexpr int BM = 128, BK = 16, TM = 8;
    constexpr int BMP = BM + 4;
    __shared__ float As[BK][BMP];
    __shared__ float Bs[BK][BN];

    const int tid = threadIdx.x;
    const int tx  = tid & 15;
    const int ty  = tid >> 4;
    const int bm0 = blockIdx.x * BM;

    const int arow = tid >> 2;
    const int acol = (tid & 3) << 2;

    constexpr int BCOLS4 = BN / 4;
    constexpr int BRPP   = 256 / BCOLS4;
    constexpr int BPASS  = BK / BRPP;
    const int brow = tid / BCOLS4;
    const int bcol = (tid % BCOLS4) << 2;

    float acc[TM][TN];
#pragma unroll
    for (int i = 0; i < TM; i++)
#pragma unroll
        for (int j = 0; j < TN; j++) acc[i][j] = 0.f;

    for (int kk = 0; kk < 128; kk += BK) {
#pragma unroll
        for (int p = 0; p < 2; p++) {
            int r = bm0 + arow + p * 64;
            float4 v = make_float4(0.f, 0.f, 0.f, 0.f);
            if (r < M) v = *(const float4*)(A + (size_t)r * 128 + kk + acol);
            As[acol + 0][arow + p * 64] = v.x;
            As[acol + 1][arow + p * 64] = v.y;
            As[acol + 2][arow + p * 64] = v.z;
            As[acol + 3][arow + p * 64] = v.w;
        }
#pragma unroll
        for (int p = 0; p < BPASS; p++) {
            int kr = brow + p * BRPP;
            *(float4*)&Bs[kr][bcol] =
                *(const float4*)(W + (size_t)(kk + kr) * BN + bcol);
        }
        __syncthreads();

#pragma unroll
        for (int k = 0; k < BK; k++) {
            float a[TM];
            float4 a0 = *(const float4*)&As[k][ty * TM];
            float4 a1 = *(const float4*)&As[k][ty * TM + 4];
            a[0] = a0.x; a[1] = a0.y; a[2] = a0.z; a[3] = a0.w;
            a[4] = a1.x; a[5] = a1.y; a[6] = a1.z; a[7] = a1.w;

            float b[TN];
            {
                float4 b0 = *(const float4*)&Bs[k][tx * TN];
                b[0] = b0.x; b[1] = b0.y; b[2] = b0.z; b[3] = b0.w;
                if (TN == 8) {
                    float4 b1v = *(const float4*)&Bs[k][tx * TN + 4];
                    b[4] = b1v.x; b[5] = b1v.y; b[6] = b1v.z; b[7] = b1v.w;
                }
            }
#pragma unroll
            for (int i = 0; i < TM; i++)
#pragma unroll
                for (int j = 0; j < TN; j++)
                    acc[i][j] = fmaf(a[i], b[j], acc[i][j]);
        }
        __syncthreads();
    }

    // epilogue: scale by dis[row], convert to fp16, store
#pragma unroll
    for (int i = 0; i < TM; i++) {
        int r = bm0 + ty * TM + i;
        if (r < M) {
            float d = g_dis[r];
            __half* cp = Ch + (size_t)r * BN + tx * TN;
            uint2 p0 = pack_h4(acc[i][0] * d, acc[i][1] * d,
                               acc[i][2] * d, acc[i][3] * d);
            *(uint2*)cp = p0;
            if (TN == 8) {
                uint2 p1 = pack_h4(acc[i][4] * d, acc[i][5] * d,
                                   acc[i][6] * d, acc[i][7] * d);
                *(uint2*)(cp + 4) = p1;
            }
        }
    }
}

// ------- agg1: warp/node, h1f = relu(dis*(sum_nbr h1s + h1s[self]) + b1) ---
__global__ void __launch_bounds__(256)
agg1_kernel(const float* __restrict__ b1, int M) {
    int w    = (blockIdx.x * 256 + threadIdx.x) >> 5;
    int lane = threadIdx.x & 31;
    if (w >= M) return;
    int beg = g_offs[w];
    int end = beg + g_deg[w];
    const uint2* h = (const uint2*)g_h1s;        // 32 x uint2 per row
    float4 s = make_float4(0.f, 0.f, 0.f, 0.f);
    acc_h4(s, __ldg(h + (size_t)w * 32 + lane)); // self term
    for (int j0 = beg; j0 < end; j0 += 32) {
        int rem = end - j0;
        int cnt = rem < 32 ? rem : 32;
        int myi = (lane < rem) ? __ldg(g_csr + j0 + lane) : 0;
        int j = 0;
        for (; j + 4 <= cnt; j += 4) {
            int s0 = __shfl_sync(0xffffffffu, myi, j);
            int s1 = __shfl_sync(0xffffffffu, myi, j + 1);
            int s2 = __shfl_sync(0xffffffffu, myi, j + 2);
            int s3 = __shfl_sync(0xffffffffu, myi, j + 3);
            uint2 v0 = __ldg(h + (size_t)s0 * 32 + lane);
            uint2 v1 = __ldg(h + (size_t)s1 * 32 + lane);
            uint2 v2 = __ldg(h + (size_t)s2 * 32 + lane);
            uint2 v3 = __ldg(h + (size_t)s3 * 32 + lane);
            acc_h4(s, v0); acc_h4(s, v1); acc_h4(s, v2); acc_h4(s, v3);
        }
        for (; j < cnt; j++) {
            int si = __shfl_sync(0xffffffffu, myi, j);
            acc_h4(s, __ldg(h + (size_t)si * 32 + lane));
        }
    }
    float  d = g_dis[w];
    float4 b = __ldg((const float4*)b1 + lane);
    float4 o;
    o.x = fmaxf(fmaf(d, s.x, b.x), 0.f);
    o.y = fmaxf(fmaf(d, s.y, b.y), 0.f);
    o.z = fmaxf(fmaf(d, s.z, b.z), 0.f);
    o.w = fmaxf(fmaf(d, s.w, b.w), 0.f);
    ((float4*)g_h1f)[(size_t)w * 32 + lane] = o;
}

// ------- agg2: half-warp/node, out = dis*(sum_nbr h2s + h2s[self]) + b2 ----
__global__ void __launch_bounds__(256)
agg2_kernel(float* __restrict__ out, const float* __restrict__ b2, int M) {
    int tid  = blockIdx.x * 256 + threadIdx.x;
    int node = tid >> 4;
    int lane = threadIdx.x & 31;
    int l16  = lane & 15;
    unsigned mask = 0xFFFFu << (lane & 16);
    bool valid = node < M;
    int beg = 0, end = 0;
    if (valid) { beg = g_offs[node]; end = beg + g_deg[node]; }
    const uint2* h = (const uint2*)g_h2s;        // 16 x uint2 per row
    float4 s = make_float4(0.f, 0.f, 0.f, 0.f);
    if (valid) acc_h4(s, __ldg(h + (size_t)node * 16 + l16));
    for (int j0 = beg; j0 < end; j0 += 16) {
        int rem = end - j0;
        int cnt = rem < 16 ? rem : 16;
        int myi = (l16 < rem) ? __ldg(g_csr + j0 + l16) : 0;
        int j = 0;
        for (; j + 4 <= cnt; j += 4) {
            int s0 = __shfl_sync(mask, myi, j,     16);
            int s1 = __shfl_sync(mask, myi, j + 1, 16);
            int s2 = __shfl_sync(mask, myi, j + 2, 16);
            int s3 = __shfl_sync(mask, myi, j + 3, 16);
            uint2 v0 = __ldg(h + (size_t)s0 * 16 + l16);
            uint2 v1 = __ldg(h + (size_t)s1 * 16 + l16);
            uint2 v2 = __ldg(h + (size_t)s2 * 16 + l16);
            uint2 v3 = __ldg(h + (size_t)s3 * 16 + l16);
            acc_h4(s, v0); acc_h4(s, v1); acc_h4(s, v2); acc_h4(s, v3);
        }
        for (; j < cnt; j++) {
            int si = __shfl_sync(mask, myi, j, 16);
            acc_h4(s, __ldg(h + (size_t)si * 16 + l16));
        }
    }
    if (valid) {
        float  d = g_dis[node];
        float4 b = __ldg((const float4*)b2 + l16);
        float4 o;
        o.x = fmaf(d, s.x, b.x);
        o.y = fmaf(d, s.y, b.y);
        o.z = fmaf(d, s.z, b.z);
        o.w = fmaf(d, s.w, b.w);
        ((float4*)out)[(size_t)node * 16 + l16] = o;
    }
}

// ---------------- launch ----------------------------------------------------
extern "C" void kernel_launch(void* const* d_in, const int* in_sizes, int n_in,
                              void* d_out, int out_size) {
    const float* x  = (const float*)d_in[0];
    const int*   ei = (const int*)  d_in[1];
    const float* W1 = (const float*)d_in[2];
    const float* b1 = (const float*)d_in[3];
    const float* W2 = (const float*)d_in[4];
    const float* b2 = (const float*)d_in[5];
    float* out = (float*)d_out;

    const int M = in_sizes[0] / FIN;
    const int E = in_sizes[1] / 2;
    const int* rows = ei;
    const int* cols = ei + E;

    __half *h1s, *h2s;
    float  *h1f;
    int* bsum;
    cudaGetSymbolAddress((void**)&h1s,  g_h1s);
    cudaGetSymbolAddress((void**)&h1f,  g_h1f);
    cudaGetSymbolAddress((void**)&h2s,  g_h2s);
    cudaGetSymbolAddress((void**)&bsum, g_bsum);

    const int nb = (M + 1023) / 1024;

    // CSR build
    zero_deg_kernel<<<(M + 255) / 256, 256>>>(M);
    degree_kernel<<<(E + 255) / 256, 256>>>(cols, E);
    scan_pass1<<<nb, 256>>>(bsum, M);
    scan_pass2<<<1, 1024>>>(bsum, nb);
    scan_pass3<<<nb, 1024>>>(bsum, M);
    place_kernel<<<(E + 255) / 256, 256>>>(rows, cols, E);

    // layer 1
    gemm_kernel<128, 8><<<(M + 127) / 128, 256>>>(x, W1, h1s, M);
    agg1_kernel<<<(M * 32 + 255) / 256, 256>>>(b1, M);

    // layer 2
    gemm_kernel<64, 4><<<(M + 127) / 128, 256>>>(h1f, W2, h2s, M);
    agg2_kernel<<<(M * 16 + 255) / 256, 256>>>(out, b2, M);
}